// round 13
// baseline (speedup 1.0000x reference)
#include <cuda_runtime.h>
#include <math.h>

// Problem constants (fixed by the reference)
#define BB   64
#define SS   128
#define HH   1024
#define EE   1024
#define EMBD 512
#define VV   32000
#define TT   50
#define KCAT 1536          // EMBD + HH
#define NGATE 4096         // 4*HH
#define GSPLIT 16          // split-K for gates GEMM (KCAT/16 = 96) -> 512 blocks
#define OSPLIT 32          // split-K for out-projection GEMM (2048/32 = 64)

typedef unsigned long long u64;

// ---- packed fp32x2 FMA (Blackwell): 2 IEEE fp32 FMAs per instruction ------
__device__ __forceinline__ u64 pack2(float v) {
    u64 r; asm("mov.b64 %0, {%1, %1};" : "=l"(r) : "f"(v)); return r;
}
__device__ __forceinline__ void ffma2(u64 &d, u64 a, u64 b) {
    asm("fma.rn.f32x2 %0, %1, %2, %0;" : "+l"(d) : "l"(a), "l"(b));
}
__device__ __forceinline__ float2 unpack2(u64 v) {
    float2 f; asm("mov.b64 {%0, %1}, %2;" : "=f"(f.x), "=f"(f.y) : "l"(v)); return f;
}

// ---------------------------------------------------------------------------
// Device scratch (static device globals — no allocation)
// ---------------------------------------------------------------------------
__device__ float g_keys[(size_t)BB * SS * HH];         // att keys [B,S,H]
__device__ float g_wcat[(size_t)NGATE * KCAT];         // [W_ih | W_hh]
__device__ float g_xcat[BB * KCAT];                    // [prev_emb | h]
__device__ float g_hc[BB * 2048];                      // [h | c_t]
__device__ float g_c[BB * HH];                         // LSTM cell state
__device__ float g_gpart[(size_t)GSPLIT * BB * NGATE]; // gates partials (L2-hot)
__device__ float g_dpart[OSPLIT * BB * EMBD];          // out-proj partials
__device__ float g_dec[BB * EMBD];                     // out-projection result
__device__ float g_scores[BB * SS];                    // attention scores

// ---------------------------------------------------------------------------
// FFMA2 SGEMM:  C[M,N] = A[M,K]*B[N,K]^T
// Block tile 64x128, TK=32, 256 threads, 8x4 micro-tile (R11 best-known).
// ---------------------------------------------------------------------------
__global__ void __launch_bounds__(256)
sgemm128(const float* __restrict__ A, int lda,
         const float* __restrict__ B, int ldb,
         float* __restrict__ C, size_t ldc, size_t splitStride, int kLen)
{
    constexpr int TM = 64, TN = 128, TK = 32;
    __shared__ float As[2][TK][TM + 4];
    __shared__ float Bs[2][TK][TN + 4];

    const int tid = threadIdx.x;
    const int m0  = blockIdx.y * TM;
    const int n0  = blockIdx.x * TN;

    A += (size_t)m0 * lda + (size_t)blockIdx.z * kLen;
    B += (size_t)n0 * ldb + (size_t)blockIdx.z * kLen;
    C += (size_t)blockIdx.z * splitStride + (size_t)m0 * ldc + n0;

    const int ar = tid >> 2;            // A row 0..63
    const int ak = (tid & 3) * 4;       // A k base {0,4,8,12} (+16)
    const int br = tid >> 1;            // B row 0..127
    const int bk = (tid & 1) * 4;       // B k base {0,4} (+8,+16,+24)
    const float* Ald = A + (size_t)ar * lda + ak;
    const float* Bld = B + (size_t)br * ldb + bk;

    float4 ra0 = *(const float4*)(Ald);
    float4 ra1 = *(const float4*)(Ald + 16);
    float4 rb0 = *(const float4*)(Bld);
    float4 rb1 = *(const float4*)(Bld + 8);
    float4 rb2 = *(const float4*)(Bld + 16);
    float4 rb3 = *(const float4*)(Bld + 24);

    const int rg = tid >> 5;            // warp -> rows rg*8..rg*8+7
    const int cg = tid & 31;            // lane -> cols cg*4..cg*4+3

    u64 accP[4][4];
#pragma unroll
    for (int i = 0; i < 4; i++)
#pragma unroll
        for (int j = 0; j < 4; j++) accP[i][j] = 0ULL;

    const int nk = kLen / TK;
    int buf = 0;

#define STORE_TILE128(bf)                                                     \
    {   As[bf][ak+ 0][ar]=ra0.x; As[bf][ak+ 1][ar]=ra0.y;                     \
        As[bf][ak+ 2][ar]=ra0.z; As[bf][ak+ 3][ar]=ra0.w;                     \
        As[bf][ak+16][ar]=ra1.x; As[bf][ak+17][ar]=ra1.y;                     \
        As[bf][ak+18][ar]=ra1.z; As[bf][ak+19][ar]=ra1.w;                     \
        Bs[bf][bk+ 0][br]=rb0.x; Bs[bf][bk+ 1][br]=rb0.y;                     \
        Bs[bf][bk+ 2][br]=rb0.z; Bs[bf][bk+ 3][br]=rb0.w;                     \
        Bs[bf][bk+ 8][br]=rb1.x; Bs[bf][bk+ 9][br]=rb1.y;                     \
        Bs[bf][bk+10][br]=rb1.z; Bs[bf][bk+11][br]=rb1.w;                     \
        Bs[bf][bk+16][br]=rb2.x; Bs[bf][bk+17][br]=rb2.y;                     \
        Bs[bf][bk+18][br]=rb2.z; Bs[bf][bk+19][br]=rb2.w;                     \
        Bs[bf][bk+24][br]=rb3.x; Bs[bf][bk+25][br]=rb3.y;                     \
        Bs[bf][bk+26][br]=rb3.z; Bs[bf][bk+27][br]=rb3.w; }

    STORE_TILE128(0);
    __syncthreads();

    for (int kt = 0; kt < nk; kt++) {
        if (kt + 1 < nk) {
            const float* Ap = Ald + (kt + 1) * TK;
            const float* Bp = Bld + (kt + 1) * TK;
            ra0 = *(const float4*)(Ap);
            ra1 = *(const float4*)(Ap + 16);
            rb0 = *(const float4*)(Bp);
            rb1 = *(const float4*)(Bp + 8);
            rb2 = *(const float4*)(Bp + 16);
            rb3 = *(const float4*)(Bp + 24);
        }
#pragma unroll
        for (int k = 0; k < TK; k++) {
            ulonglong2 aLo = *(const ulonglong2*)&As[buf][k][rg * 8];
            ulonglong2 aHi = *(const ulonglong2*)&As[buf][k][rg * 8 + 4];
            float4 b = *(const float4*)&Bs[buf][k][cg * 4];
            u64 b0 = pack2(b.x), b1 = pack2(b.y), b2 = pack2(b.z), b3 = pack2(b.w);
            ffma2(accP[0][0], aLo.x, b0); ffma2(accP[0][1], aLo.x, b1);
            ffma2(accP[0][2], aLo.x, b2); ffma2(accP[0][3], aLo.x, b3);
            ffma2(accP[1][0], aLo.y, b0); ffma2(accP[1][1], aLo.y, b1);
            ffma2(accP[1][2], aLo.y, b2); ffma2(accP[1][3], aLo.y, b3);
            ffma2(accP[2][0], aHi.x, b0); ffma2(accP[2][1], aHi.x, b1);
            ffma2(accP[2][2], aHi.x, b2); ffma2(accP[2][3], aHi.x, b3);
            ffma2(accP[3][0], aHi.y, b0); ffma2(accP[3][1], aHi.y, b1);
            ffma2(accP[3][2], aHi.y, b2); ffma2(accP[3][3], aHi.y, b3);
        }
        if (kt + 1 < nk) {
            STORE_TILE128(buf ^ 1);
            __syncthreads();
            buf ^= 1;
        }
    }
#undef STORE_TILE128

#pragma unroll
    for (int p = 0; p < 4; p++) {
        float2 c0 = unpack2(accP[p][0]);
        float2 c1 = unpack2(accP[p][1]);
        float2 c2 = unpack2(accP[p][2]);
        float2 c3 = unpack2(accP[p][3]);
        *(float4*)(C + (size_t)(rg * 8 + 2 * p)     * ldc + cg * 4)
            = make_float4(c0.x, c1.x, c2.x, c3.x);
        *(float4*)(C + (size_t)(rg * 8 + 2 * p + 1) * ldc + cg * 4)
            = make_float4(c0.y, c1.y, c2.y, c3.y);
    }
}

// ---------------------------------------------------------------------------
// Small FFMA2 SGEMM (TN=64, 4x4 micro-tile) — out-projection AND vocab
// (vocab uses it with grid (500,1): more blocks -> more outstanding loads ->
//  higher achieved DRAM bandwidth on the 65.5MB W_vocab stream)
// ---------------------------------------------------------------------------
__global__ void __launch_bounds__(256)
sgemm64(const float* __restrict__ A, int lda,
        const float* __restrict__ B, int ldb,
        float* __restrict__ C, size_t ldc, size_t splitStride, int kLen)
{
    constexpr int TM = 64, TN = 64, TK = 32;
    __shared__ float As[2][TK][TM + 4];
    __shared__ float Bs[2][TK][TN + 4];

    const int tid = threadIdx.x;
    const int m0  = blockIdx.y * TM;
    const int n0  = blockIdx.x * TN;

    A += (size_t)m0 * lda + (size_t)blockIdx.z * kLen;
    B += (size_t)n0 * ldb + (size_t)blockIdx.z * kLen;
    C += (size_t)blockIdx.z * splitStride + (size_t)m0 * ldc + n0;

    const int lr  = tid >> 2;
    const int lc4 = tid & 3;
    const int tx  = tid & 15;
    const int ty  = tid >> 4;

    const float* Ald = A + (size_t)lr * lda + lc4 * 4;
    const float* Bld = B + (size_t)lr * ldb + lc4 * 4;

    float4 ra0 = *(const float4*)(Ald);
    float4 ra1 = *(const float4*)(Ald + 16);
    float4 rb0 = *(const float4*)(Bld);
    float4 rb1 = *(const float4*)(Bld + 16);

    u64 accP[2][4];
#pragma unroll
    for (int i = 0; i < 2; i++)
#pragma unroll
        for (int j = 0; j < 4; j++) accP[i][j] = 0ULL;

    const int nk = kLen / TK;
    int buf = 0;

#define STORE_TILE(bf)                                                        \
    {   int kk0 = lc4 * 4;                                                    \
        As[bf][kk0+ 0][lr]=ra0.x; As[bf][kk0+ 1][lr]=ra0.y;                   \
        As[bf][kk0+ 2][lr]=ra0.z; As[bf][kk0+ 3][lr]=ra0.w;                   \
        As[bf][kk0+16][lr]=ra1.x; As[bf][kk0+17][lr]=ra1.y;                   \
        As[bf][kk0+18][lr]=ra1.z; As[bf][kk0+19][lr]=ra1.w;                   \
        Bs[bf][kk0+ 0][lr]=rb0.x; Bs[bf][kk0+ 1][lr]=rb0.y;                   \
        Bs[bf][kk0+ 2][lr]=rb0.z; Bs[bf][kk0+ 3][lr]=rb0.w;                   \
        Bs[bf][kk0+16][lr]=rb1.x; Bs[bf][kk0+17][lr]=rb1.y;                   \
        Bs[bf][kk0+18][lr]=rb1.z; Bs[bf][kk0+19][lr]=rb1.w; }

    STORE_TILE(0);
    __syncthreads();

    for (int kt = 0; kt < nk; kt++) {
        if (kt + 1 < nk) {
            const float* Ap = Ald + (kt + 1) * TK;
            const float* Bp = Bld + (kt + 1) * TK;
            ra0 = *(const float4*)(Ap);
            ra1 = *(const float4*)(Ap + 16);
            rb0 = *(const float4*)(Bp);
            rb1 = *(const float4*)(Bp + 16);
        }
#pragma unroll
        for (int k = 0; k < TK; k++) {
            ulonglong2 aP = *(const ulonglong2*)&As[buf][k][ty * 4];
            float4 b = *(const float4*)&Bs[buf][k][tx * 4];
            u64 b0 = pack2(b.x), b1 = pack2(b.y), b2 = pack2(b.z), b3 = pack2(b.w);
            ffma2(accP[0][0], aP.x, b0); ffma2(accP[0][1], aP.x, b1);
            ffma2(accP[0][2], aP.x, b2); ffma2(accP[0][3], aP.x, b3);
            ffma2(accP[1][0], aP.y, b0); ffma2(accP[1][1], aP.y, b1);
            ffma2(accP[1][2], aP.y, b2); ffma2(accP[1][3], aP.y, b3);
        }
        if (kt + 1 < nk) {
            STORE_TILE(buf ^ 1);
            __syncthreads();
            buf ^= 1;
        }
    }
#undef STORE_TILE

#pragma unroll
    for (int p = 0; p < 2; p++) {
        float2 c0 = unpack2(accP[p][0]);
        float2 c1 = unpack2(accP[p][1]);
        float2 c2 = unpack2(accP[p][2]);
        float2 c3 = unpack2(accP[p][3]);
        *(float4*)(C + (size_t)(ty * 4 + 2 * p)     * ldc + tx * 4)
            = make_float4(c0.x, c1.x, c2.x, c3.x);
        *(float4*)(C + (size_t)(ty * 4 + 2 * p + 1) * ldc + tx * 4)
            = make_float4(c0.y, c1.y, c2.y, c3.y);
    }
}

// ---------------------------------------------------------------------------
// Setup kernels
// ---------------------------------------------------------------------------
__global__ void build_wcat(const float* __restrict__ W_ih,
                           const float* __restrict__ W_hh)
{
    size_t total = (size_t)NGATE * KCAT;
    for (size_t i = (size_t)blockIdx.x * blockDim.x + threadIdx.x; i < total;
         i += (size_t)gridDim.x * blockDim.x) {
        int j = (int)(i / KCAT);
        int k = (int)(i % KCAT);
        g_wcat[i] = (k < EMBD) ? W_ih[(size_t)j * EMBD + k]
                               : W_hh[(size_t)j * HH + (k - EMBD)];
    }
}

__global__ void init_state(const float* __restrict__ dec_init)
{
    int idx = blockIdx.x * blockDim.x + threadIdx.x;   // B*H
    int b = idx >> 10, j = idx & 1023;
    float h0 = dec_init[idx];
    g_hc[b * 2048 + j] = h0;
    g_xcat[b * KCAT + EMBD + j] = h0;
    g_c[idx] = dec_init[BB * HH + idx];
    if (j < EMBD) g_xcat[b * KCAT + j] = 0.f;
}

// ---------------------------------------------------------------------------
// LSTM cell (float4): sum GSPLIT gate partials + bias, apply nonlinearity
// ---------------------------------------------------------------------------
__device__ __forceinline__ float sigf(float x) { return 1.f / (1.f + expf(-x)); }

__global__ void __launch_bounds__(256)
lstm_cell(const float* __restrict__ b_lstm)
{
    int q = blockIdx.x * blockDim.x + threadIdx.x;     // 0..B*H/4-1
    int base = q * 4;
    int b = base >> 10, j = base & 1023;
    const float* gp = g_gpart + (size_t)b * NGATE;
    const size_t SP = (size_t)BB * NGATE;

    float4 ig = *(const float4*)&b_lstm[j];
    float4 fg = *(const float4*)&b_lstm[1024 + j];
    float4 gg = *(const float4*)&b_lstm[2048 + j];
    float4 og = *(const float4*)&b_lstm[3072 + j];
#pragma unroll
    for (int s = 0; s < GSPLIT; s++) {
        const float* p = gp + s * SP;
        float4 v;
        v = *(const float4*)&p[j];        ig.x+=v.x; ig.y+=v.y; ig.z+=v.z; ig.w+=v.w;
        v = *(const float4*)&p[1024 + j]; fg.x+=v.x; fg.y+=v.y; fg.z+=v.z; fg.w+=v.w;
        v = *(const float4*)&p[2048 + j]; gg.x+=v.x; gg.y+=v.y; gg.z+=v.z; gg.w+=v.w;
        v = *(const float4*)&p[3072 + j]; og.x+=v.x; og.y+=v.y; og.z+=v.z; og.w+=v.w;
    }
    float4 cold = *(const float4*)&g_c[base];
    float4 c, h;
    c.x = sigf(fg.x) * cold.x + sigf(ig.x) * tanhf(gg.x);
    c.y = sigf(fg.y) * cold.y + sigf(ig.y) * tanhf(gg.y);
    c.z = sigf(fg.z) * cold.z + sigf(ig.z) * tanhf(gg.z);
    c.w = sigf(fg.w) * cold.w + sigf(ig.w) * tanhf(gg.w);
    h.x = sigf(og.x) * tanhf(c.x);
    h.y = sigf(og.y) * tanhf(c.y);
    h.z = sigf(og.z) * tanhf(c.z);
    h.w = sigf(og.w) * tanhf(c.w);
    *(float4*)&g_c[base] = c;
    *(float4*)&g_hc[b * 2048 + j] = h;
    *(float4*)&g_xcat[b * KCAT + EMBD + j] = h;
}

// ---------------------------------------------------------------------------
// Attention scores: grid (16, B); one score row per warp.
// MASKED: rows s >= enc_len[b] are never read downstream (context applies
// the mask), so skip both the compute and the 4KB key-row read.
// ---------------------------------------------------------------------------
__global__ void __launch_bounds__(256)
attn_scores(const int* __restrict__ enc_len)
{
    int b = blockIdx.y;
    int tid = threadIdx.x, warp = tid >> 5, lane = tid & 31;
    __shared__ float4 sh4[HH / 4];

    const float4* h4 = (const float4*)&g_hc[b * 2048];
    sh4[tid] = h4[tid];
    __syncthreads();

    int s = blockIdx.x * 8 + warp;
    if (s >= enc_len[b]) return;              // masked row: skip 4KB read

    const float4* k4 = (const float4*)&g_keys[((size_t)b * SS + s) * HH];
    float acc = 0.f;
#pragma unroll
    for (int i = 0; i < 8; i++) {
        float4 kv = k4[lane + 32 * i];
        float4 hv = sh4[lane + 32 * i];
        acc = fmaf(kv.x, hv.x, acc);
        acc = fmaf(kv.y, hv.y, acc);
        acc = fmaf(kv.z, hv.z, acc);
        acc = fmaf(kv.w, hv.w, acc);
    }
#pragma unroll
    for (int o = 16; o; o >>= 1) acc += __shfl_xor_sync(0xffffffffu, acc, o);
    if (lane == 0) g_scores[b * SS + s] = acc;
}

// ---------------------------------------------------------------------------
// Attention context (softmax fused, recomputed per block): grid (4, B)
// ---------------------------------------------------------------------------
__global__ void __launch_bounds__(256)
attn_context(const float* __restrict__ enc, const int* __restrict__ enc_len)
{
    int b = blockIdx.y, e0 = blockIdx.x * 256;
    int tid = threadIdx.x, warp = tid >> 5, lane = tid & 31;
    __shared__ float sa[SS];
    __shared__ float red[8];
    __shared__ float bc;

    int len = enc_len[b];
    float v = -1e9f;
    if (tid < SS) {
        v = (tid < len) ? g_scores[b * SS + tid] : -1e9f;
        sa[tid] = v;
    }
    float m = v;
#pragma unroll
    for (int o = 16; o; o >>= 1) m = fmaxf(m, __shfl_xor_sync(0xffffffffu, m, o));
    if (lane == 0) red[warp] = m;
    __syncthreads();
    if (tid == 0) {
        float mm = red[0];
        for (int i = 1; i < 4; i++) mm = fmaxf(mm, red[i]);
        bc = mm;
    }
    __syncthreads();
    float mx = bc;

    float e = (tid < SS) ? expf(v - mx) : 0.f;
    float s2 = e;
#pragma unroll
    for (int o = 16; o; o >>= 1) s2 += __shfl_xor_sync(0xffffffffu, s2, o);
    __syncthreads();
    if (lane == 0) red[warp] = s2;
    __syncthreads();
    if (tid == 0) bc = red[0] + red[1] + red[2] + red[3];
    __syncthreads();
    float inv = 1.f / bc;
    if (tid < SS) sa[tid] = e * inv;
    __syncthreads();

    const float* ep = enc + ((size_t)b * SS) * EE + e0 + tid;
    float acc = 0.f;
    int s = 0;
    for (; s + 8 <= len; s += 8) {
        float x0 = ep[(size_t)(s + 0) * EE];
        float x1 = ep[(size_t)(s + 1) * EE];
        float x2 = ep[(size_t)(s + 2) * EE];
        float x3 = ep[(size_t)(s + 3) * EE];
        float x4 = ep[(size_t)(s + 4) * EE];
        float x5 = ep[(size_t)(s + 5) * EE];
        float x6 = ep[(size_t)(s + 6) * EE];
        float x7 = ep[(size_t)(s + 7) * EE];
        acc = fmaf(sa[s + 0], x0, acc);
        acc = fmaf(sa[s + 1], x1, acc);
        acc = fmaf(sa[s + 2], x2, acc);
        acc = fmaf(sa[s + 3], x3, acc);
        acc = fmaf(sa[s + 4], x4, acc);
        acc = fmaf(sa[s + 5], x5, acc);
        acc = fmaf(sa[s + 6], x6, acc);
        acc = fmaf(sa[s + 7], x7, acc);
    }
    for (; s < len; s++) acc = fmaf(sa[s], ep[(size_t)s * EE], acc);
    g_hc[b * 2048 + HH + e0 + tid] = acc;
}

// ---------------------------------------------------------------------------
// Reduce out-projection split-K partials (float4)
// ---------------------------------------------------------------------------
__global__ void __launch_bounds__(256)
reduce_dec()
{
    int q = blockIdx.x * blockDim.x + threadIdx.x;
    float4 a = make_float4(0.f, 0.f, 0.f, 0.f);
#pragma unroll
    for (int s = 0; s < OSPLIT; s++) {
        float4 v = *(const float4*)&g_dpart[(size_t)s * BB * EMBD + q * 4];
        a.x += v.x; a.y += v.y; a.z += v.z; a.w += v.w;
    }
    *(float4*)&g_dec[q * 4] = a;
}

// ---------------------------------------------------------------------------
// Greedy argmax over logits row + embedding gather
// ---------------------------------------------------------------------------
__global__ void __launch_bounds__(1024)
argmax_embed(const float* __restrict__ logits, const float* __restrict__ emb, int t)
{
    int b = blockIdx.x;
    const float4* row4 = (const float4*)(logits + ((size_t)b * TT + t) * VV);
    int tid = threadIdx.x;

    float bv = -INFINITY;
    int   bi = 0x7fffffff;
#pragma unroll
    for (int j = 0; j < 8; j++) {
        int v4 = j * 1024 + tid;
        if (v4 < VV / 4) {
            float4 x = row4[v4];
            int base = v4 * 4;
            if (x.x > bv || (x.x == bv && base     < bi)) { bv = x.x; bi = base;     }
            if (x.y > bv || (x.y == bv && base + 1 < bi)) { bv = x.y; bi = base + 1; }
            if (x.z > bv || (x.z == bv && base + 2 < bi)) { bv = x.z; bi = base + 2; }
            if (x.w > bv || (x.w == bv && base + 3 < bi)) { bv = x.w; bi = base + 3; }
        }
    }
#pragma unroll
    for (int o = 16; o; o >>= 1) {
        float ov = __shfl_xor_sync(0xffffffffu, bv, o);
        int   oi = __shfl_xor_sync(0xffffffffu, bi, o);
        if (ov > bv || (ov == bv && oi < bi)) { bv = ov; bi = oi; }
    }
    __shared__ float sv[32];
    __shared__ int   si[32];
    __shared__ int   ssym;
    int warp = tid >> 5, lane = tid & 31;
    if (lane == 0) { sv[warp] = bv; si[warp] = bi; }
    __syncthreads();
    if (warp == 0) {
        bv = sv[lane]; bi = si[lane];
#pragma unroll
        for (int o = 16; o; o >>= 1) {
            float ov = __shfl_xor_sync(0xffffffffu, bv, o);
            int   oi = __shfl_xor_sync(0xffffffffu, bi, o);
            if (ov > bv || (ov == bv && oi < bi)) { bv = ov; bi = oi; }
        }
        if (lane == 0) ssym = bi;
    }
    __syncthreads();
    int sym = ssym;
    if (tid < EMBD / 4) {
        const float4* er = (const float4*)(emb + (size_t)sym * EMBD);
        ((float4*)&g_xcat[b * KCAT])[tid] = er[tid];
    }
}

// ---------------------------------------------------------------------------
// Fused in-place log-softmax over each [VV] row of d_out
// ---------------------------------------------------------------------------
__global__ void __launch_bounds__(1024)
logsoftmax_rows(float* __restrict__ out)
{
    float* p = out + (size_t)blockIdx.x * VV;
    int tid = threadIdx.x;

    float x[32];
    float mx = -INFINITY;
#pragma unroll
    for (int i = 0; i < 32; i++) {
        int v = tid + (i << 10);
        x[i] = (v < VV) ? p[v] : -INFINITY;
        mx = fmaxf(mx, x[i]);
    }
    __shared__ float red[32];
    __shared__ float bc;
#pragma unroll
    for (int o = 16; o; o >>= 1) mx = fmaxf(mx, __shfl_xor_sync(0xffffffffu, mx, o));
    if ((tid & 31) == 0) red[tid >> 5] = mx;
    __syncthreads();
    if (tid < 32) {
        float m = red[tid];
#pragma unroll
        for (int o = 16; o; o >>= 1) m = fmaxf(m, __shfl_xor_sync(0xffffffffu, m, o));
        if (tid == 0) bc = m;
    }
    __syncthreads();
    float M = bc;

    float s = 0.f;
#pragma unroll
    for (int i = 0; i < 32; i++) s += expf(x[i] - M);
    __syncthreads();
#pragma unroll
    for (int o = 16; o; o >>= 1) s += __shfl_xor_sync(0xffffffffu, s, o);
    if ((tid & 31) == 0) red[tid >> 5] = s;
    __syncthreads();
    if (tid < 32) {
        float m = red[tid];
#pragma unroll
        for (int o = 16; o; o >>= 1) m += __shfl_xor_sync(0xffffffffu, m, o);
        if (tid == 0) bc = m;
    }
    __syncthreads();
    float lz = M + logf(bc);
#pragma unroll
    for (int i = 0; i < 32; i++) {
        int v = tid + (i << 10);
        if (v < VV) p[v] = x[i] - lz;
    }
}

__global__ void fill_tail(float* __restrict__ p, long n, float val)
{
    long i = (long)blockIdx.x * blockDim.x + threadIdx.x;
    if (i < n) p[i] = val;
}

// ---------------------------------------------------------------------------
// Launch
// ---------------------------------------------------------------------------
extern "C" void kernel_launch(void* const* d_in, const int* in_sizes, int n_in,
                              void* d_out, int out_size)
{
    const float* dec_init  = (const float*)d_in[0];
    const float* enc       = (const float*)d_in[1];
    const int*   enc_len   = (const int*)d_in[2];
    /* d_in[3] = tgt (unused in eval mode) */
    const float* W_ih      = (const float*)d_in[4];
    const float* W_hh      = (const float*)d_in[5];
    const float* b_lstm    = (const float*)d_in[6];
    const float* W_attproj = (const float*)d_in[7];
    const float* W_out     = (const float*)d_in[8];
    const float* W_vocab   = (const float*)d_in[9];
    const float* emb       = (const float*)d_in[10];
    float* out = (float*)d_out;

    void *p_keys, *p_wcat, *p_xcat, *p_hc, *p_gpart, *p_dpart, *p_dec;
    cudaGetSymbolAddress(&p_keys,  g_keys);
    cudaGetSymbolAddress(&p_wcat,  g_wcat);
    cudaGetSymbolAddress(&p_xcat,  g_xcat);
    cudaGetSymbolAddress(&p_hc,    g_hc);
    cudaGetSymbolAddress(&p_gpart, g_gpart);
    cudaGetSymbolAddress(&p_dpart, g_dpart);
    cudaGetSymbolAddress(&p_dec,   g_dec);

    // one-time setup
    build_wcat<<<2048, 256>>>(W_ih, W_hh);
    init_state<<<(BB * HH) / 256, 256>>>(dec_init);
    // keys[B*S, H] = enc[B*S, E] @ W_attproj^T   (grid 8 x 128 = 1024 blocks)
    sgemm128<<<dim3(HH / 128, (BB * SS) / 64, 1), 256>>>(
        enc, EE, W_attproj, EE, (float*)p_keys, HH, 0, EE);

    for (int t = 0; t < TT; t++) {
        // gates partials: split-K x16  (32 x 16 = 512 blocks, kLen=96)
        sgemm128<<<dim3(NGATE / 128, 1, GSPLIT), 256>>>(
            (const float*)p_xcat, KCAT, (const float*)p_wcat, KCAT,
            (float*)p_gpart, NGATE, (size_t)BB * NGATE, KCAT / GSPLIT);
        lstm_cell<<<(BB * HH / 4) / 256, 256>>>(b_lstm);
        attn_scores<<<dim3(16, BB), 256>>>(enc_len);
        attn_context<<<dim3(4, BB), 256>>>(enc, enc_len);
        // dec partials: split-K x32  (8 x 32 = 256 blocks, kLen=64)
        sgemm64<<<dim3(EMBD / 64, 1, OSPLIT), 256>>>(
            (const float*)p_hc, 2048, W_out, 2048,
            (float*)p_dpart, EMBD, (size_t)BB * EMBD, 2048 / OSPLIT);
        reduce_dec<<<(BB * EMBD / 4) / 256, 256>>>();
        // vocab logits straight into d_out[b, t, :]  (500 blocks, TN=64)
        sgemm64<<<dim3(VV / 64, 1, 1), 256>>>(
            (const float*)p_dec, EMBD, W_vocab, EMBD,
            out + (size_t)t * VV, (size_t)TT * VV, 0, EMBD);
        argmax_embed<<<BB, 1024>>>(out, emb, t);
    }

    // final log-softmax in place over all B*T rows
    logsoftmax_rows<<<BB * TT, 1024>>>(out);

    // tgt_len output: always T (== 50) per the reference's final where()
    long extra = (long)out_size - (long)BB * TT * VV;
    if (extra > 0)
        fill_tail<<<(unsigned)((extra + 255) / 256), 256>>>(
            out + (size_t)BB * TT * VV, extra, 50.0f);
}

// round 14
// speedup vs baseline: 1.2074x; 1.2074x over previous
#include <cuda_runtime.h>
#include <math.h>

// Problem constants (fixed by the reference)
#define BB   64
#define SS   128
#define HH   1024
#define EE   1024
#define EMBD 512
#define VV   32000
#define TT   50
#define KCAT 1536          // EMBD + HH
#define NGATE 4096         // 4*HH
#define GSPLIT 8           // split-K for gates GEMM (KCAT/8 = 192)
#define OSPLIT 32          // split-K for out-projection GEMM (2048/32 = 64)
#define VTILES (VV / 128)  // 250 vocab column tiles

typedef unsigned long long u64;

// ---- packed fp32x2 FMA (Blackwell): 2 IEEE fp32 FMAs per instruction ------
__device__ __forceinline__ u64 pack2(float v) {
    u64 r; asm("mov.b64 %0, {%1, %1};" : "=l"(r) : "f"(v)); return r;
}
__device__ __forceinline__ void ffma2(u64 &d, u64 a, u64 b) {
    asm("fma.rn.f32x2 %0, %1, %2, %0;" : "+l"(d) : "l"(a), "l"(b));
}
__device__ __forceinline__ float2 unpack2(u64 v) {
    float2 f; asm("mov.b64 {%0, %1}, %2;" : "=f"(f.x), "=f"(f.y) : "l"(v)); return f;
}

// ---------------------------------------------------------------------------
// Device scratch (static device globals — no allocation)
// ---------------------------------------------------------------------------
__device__ float g_keys[(size_t)BB * SS * HH];         // att keys [B,S,H]
__device__ float g_wcat[(size_t)NGATE * KCAT];         // [W_ih | W_hh]
__device__ float g_xcat[BB * KCAT];                    // [prev_emb | h]
__device__ float g_hc[BB * 2048];                      // [h | c_t]
__device__ float g_c[BB * HH];                         // LSTM cell state
__device__ float g_gpart[(size_t)GSPLIT * BB * NGATE]; // gates partials
__device__ float g_dpart[OSPLIT * BB * EMBD];          // out-proj partials
__device__ float g_dec[BB * EMBD];                     // out-projection result
__device__ float g_scores[BB * SS];                    // attention scores
__device__ float2 g_pmax[VTILES * BB];                 // per-tile row (max,idx)

// ---------------------------------------------------------------------------
// FFMA2 SGEMM:  C[M,N] = A[M,K]*B[N,K]^T
// Block tile 64x128, TK=32, 256 threads, 8x4 micro-tile (best-known config).
// Optional extras:
//   mlen: if non-null, m-tiles whose encoder row-offset >= enc_len[b] are
//         skipped entirely (keys GEMM; those rows are never read downstream).
//   pmax: if non-null (vocab GEMM, grid.y==1), emit per-row (max, argmax)
//         over this block's 128-col tile with exact fp32 compare and
//         lowest-index tie-break.
// ---------------------------------------------------------------------------
__global__ void __launch_bounds__(256)
sgemm128(const float* __restrict__ A, int lda,
         const float* __restrict__ B, int ldb,
         float* __restrict__ C, size_t ldc, size_t splitStride, int kLen,
         const int* __restrict__ mlen, float2* __restrict__ pmax)
{
    constexpr int TM = 64, TN = 128, TK = 32;
    __shared__ float As[2][TK][TM + 4];
    __shared__ float Bs[2][TK][TN + 4];

    const int tid = threadIdx.x;
    const int m0  = blockIdx.y * TM;
    const int n0  = blockIdx.x * TN;

    if (mlen) {                          // keys GEMM: skip fully-masked m-tile
        int bb  = m0 >> 7;               // batch row (128 s-rows per b)
        int off = m0 & 127;              // s-offset of this tile
        if (off >= mlen[bb]) return;     // uniform for the whole block
    }

    A += (size_t)m0 * lda + (size_t)blockIdx.z * kLen;
    B += (size_t)n0 * ldb + (size_t)blockIdx.z * kLen;
    C += (size_t)blockIdx.z * splitStride + (size_t)m0 * ldc + n0;

    const int ar = tid >> 2;            // A row 0..63
    const int ak = (tid & 3) * 4;       // A k base {0,4,8,12} (+16)
    const int br = tid >> 1;            // B row 0..127
    const int bk = (tid & 1) * 4;       // B k base {0,4} (+8,+16,+24)
    const float* Ald = A + (size_t)ar * lda + ak;
    const float* Bld = B + (size_t)br * ldb + bk;

    float4 ra0 = *(const float4*)(Ald);
    float4 ra1 = *(const float4*)(Ald + 16);
    float4 rb0 = *(const float4*)(Bld);
    float4 rb1 = *(const float4*)(Bld + 8);
    float4 rb2 = *(const float4*)(Bld + 16);
    float4 rb3 = *(const float4*)(Bld + 24);

    const int rg = tid >> 5;            // warp -> rows rg*8..rg*8+7
    const int cg = tid & 31;            // lane -> cols cg*4..cg*4+3

    u64 accP[4][4];
#pragma unroll
    for (int i = 0; i < 4; i++)
#pragma unroll
        for (int j = 0; j < 4; j++) accP[i][j] = 0ULL;

    const int nk = kLen / TK;
    int buf = 0;

#define STORE_TILE128(bf)                                                     \
    {   As[bf][ak+ 0][ar]=ra0.x; As[bf][ak+ 1][ar]=ra0.y;                     \
        As[bf][ak+ 2][ar]=ra0.z; As[bf][ak+ 3][ar]=ra0.w;                     \
        As[bf][ak+16][ar]=ra1.x; As[bf][ak+17][ar]=ra1.y;                     \
        As[bf][ak+18][ar]=ra1.z; As[bf][ak+19][ar]=ra1.w;                     \
        Bs[bf][bk+ 0][br]=rb0.x; Bs[bf][bk+ 1][br]=rb0.y;                     \
        Bs[bf][bk+ 2][br]=rb0.z; Bs[bf][bk+ 3][br]=rb0.w;                     \
        Bs[bf][bk+ 8][br]=rb1.x; Bs[bf][bk+ 9][br]=rb1.y;                     \
        Bs[bf][bk+10][br]=rb1.z; Bs[bf][bk+11][br]=rb1.w;                     \
        Bs[bf][bk+16][br]=rb2.x; Bs[bf][bk+17][br]=rb2.y;                     \
        Bs[bf][bk+18][br]=rb2.z; Bs[bf][bk+19][br]=rb2.w;                     \
        Bs[bf][bk+24][br]=rb3.x; Bs[bf][bk+25][br]=rb3.y;                     \
        Bs[bf][bk+26][br]=rb3.z; Bs[bf][bk+27][br]=rb3.w; }

    STORE_TILE128(0);
    __syncthreads();

    for (int kt = 0; kt < nk; kt++) {
        if (kt + 1 < nk) {
            const float* Ap = Ald + (kt + 1) * TK;
            const float* Bp = Bld + (kt + 1) * TK;
            ra0 = *(const float4*)(Ap);
            ra1 = *(const float4*)(Ap + 16);
            rb0 = *(const float4*)(Bp);
            rb1 = *(const float4*)(Bp + 8);
            rb2 = *(const float4*)(Bp + 16);
            rb3 = *(const float4*)(Bp + 24);
        }
#pragma unroll
        for (int k = 0; k < TK; k++) {
            ulonglong2 aLo = *(const ulonglong2*)&As[buf][k][rg * 8];
            ulonglong2 aHi = *(const ulonglong2*)&As[buf][k][rg * 8 + 4];
            float4 b = *(const float4*)&Bs[buf][k][cg * 4];
            u64 b0 = pack2(b.x), b1 = pack2(b.y), b2 = pack2(b.z), b3 = pack2(b.w);
            ffma2(accP[0][0], aLo.x, b0); ffma2(accP[0][1], aLo.x, b1);
            ffma2(accP[0][2], aLo.x, b2); ffma2(accP[0][3], aLo.x, b3);
            ffma2(accP[1][0], aLo.y, b0); ffma2(accP[1][1], aLo.y, b1);
            ffma2(accP[1][2], aLo.y, b2); ffma2(accP[1][3], aLo.y, b3);
            ffma2(accP[2][0], aHi.x, b0); ffma2(accP[2][1], aHi.x, b1);
            ffma2(accP[2][2], aHi.x, b2); ffma2(accP[2][3], aHi.x, b3);
            ffma2(accP[3][0], aHi.y, b0); ffma2(accP[3][1], aHi.y, b1);
            ffma2(accP[3][2], aHi.y, b2); ffma2(accP[3][3], aHi.y, b3);
        }
        if (kt + 1 < nk) {
            STORE_TILE128(buf ^ 1);
            __syncthreads();
            buf ^= 1;
        }
    }
#undef STORE_TILE128

#pragma unroll
    for (int p = 0; p < 4; p++) {
        float2 c0 = unpack2(accP[p][0]);
        float2 c1 = unpack2(accP[p][1]);
        float2 c2 = unpack2(accP[p][2]);
        float2 c3 = unpack2(accP[p][3]);
        float4 lo = make_float4(c0.x, c1.x, c2.x, c3.x);   // row rg*8+2p
        float4 hi = make_float4(c0.y, c1.y, c2.y, c3.y);   // row rg*8+2p+1
        *(float4*)(C + (size_t)(rg * 8 + 2 * p)     * ldc + cg * 4) = lo;
        *(float4*)(C + (size_t)(rg * 8 + 2 * p + 1) * ldc + cg * 4) = hi;

        if (pmax) {
            // per-row (max, lowest argmax) over the 128-col tile
#pragma unroll
            for (int half = 0; half < 2; half++) {
                float4 v = half ? hi : lo;
                float mv = v.x; int mi = n0 + cg * 4;
                if (v.y > mv) { mv = v.y; mi = n0 + cg * 4 + 1; }
                if (v.z > mv) { mv = v.z; mi = n0 + cg * 4 + 2; }
                if (v.w > mv) { mv = v.w; mi = n0 + cg * 4 + 3; }
#pragma unroll
                for (int o = 16; o; o >>= 1) {
                    float ov = __shfl_xor_sync(0xffffffffu, mv, o);
                    int   oi = __shfl_xor_sync(0xffffffffu, mi, o);
                    if (ov > mv || (ov == mv && oi < mi)) { mv = ov; mi = oi; }
                }
                if (cg == 0)
                    g_pmax[blockIdx.x * BB + rg * 8 + 2 * p + half]
                        = make_float2(mv, __int_as_float(mi));
            }
        }
    }
}

// ---------------------------------------------------------------------------
// Small FFMA2 SGEMM (TN=64, 4x4 micro-tile) — only the tiny out-projection
// ---------------------------------------------------------------------------
__global__ void __launch_bounds__(256)
sgemm64(const float* __restrict__ A, int lda,
        const float* __restrict__ B, int ldb,
        float* __restrict__ C, size_t ldc, size_t splitStride, int kLen)
{
    constexpr int TM = 64, TN = 64, TK = 32;
    __shared__ float As[2][TK][TM + 4];
    __shared__ float Bs[2][TK][TN + 4];

    const int tid = threadIdx.x;
    const int m0  = blockIdx.y * TM;
    const int n0  = blockIdx.x * TN;

    A += (size_t)m0 * lda + (size_t)blockIdx.z * kLen;
    B += (size_t)n0 * ldb + (size_t)blockIdx.z * kLen;
    C += (size_t)blockIdx.z * splitStride + (size_t)m0 * ldc + n0;

    const int lr  = tid >> 2;
    const int lc4 = tid & 3;
    const int tx  = tid & 15;
    const int ty  = tid >> 4;

    const float* Ald = A + (size_t)lr * lda + lc4 * 4;
    const float* Bld = B + (size_t)lr * ldb + lc4 * 4;

    float4 ra0 = *(const float4*)(Ald);
    float4 ra1 = *(const float4*)(Ald + 16);
    float4 rb0 = *(const float4*)(Bld);
    float4 rb1 = *(const float4*)(Bld + 16);

    u64 accP[2][4];
#pragma unroll
    for (int i = 0; i < 2; i++)
#pragma unroll
        for (int j = 0; j < 4; j++) accP[i][j] = 0ULL;

    const int nk = kLen / TK;
    int buf = 0;

#define STORE_TILE(bf)                                                        \
    {   int kk0 = lc4 * 4;                                                    \
        As[bf][kk0+ 0][lr]=ra0.x; As[bf][kk0+ 1][lr]=ra0.y;                   \
        As[bf][kk0+ 2][lr]=ra0.z; As[bf][kk0+ 3][lr]=ra0.w;                   \
        As[bf][kk0+16][lr]=ra1.x; As[bf][kk0+17][lr]=ra1.y;                   \
        As[bf][kk0+18][lr]=ra1.z; As[bf][kk0+19][lr]=ra1.w;                   \
        Bs[bf][kk0+ 0][lr]=rb0.x; Bs[bf][kk0+ 1][lr]=rb0.y;                   \
        Bs[bf][kk0+ 2][lr]=rb0.z; Bs[bf][kk0+ 3][lr]=rb0.w;                   \
        Bs[bf][kk0+16][lr]=rb1.x; Bs[bf][kk0+17][lr]=rb1.y;                   \
        Bs[bf][kk0+18][lr]=rb1.z; Bs[bf][kk0+19][lr]=rb1.w; }

    STORE_TILE(0);
    __syncthreads();

    for (int kt = 0; kt < nk; kt++) {
        if (kt + 1 < nk) {
            const float* Ap = Ald + (kt + 1) * TK;
            const float* Bp = Bld + (kt + 1) * TK;
            ra0 = *(const float4*)(Ap);
            ra1 = *(const float4*)(Ap + 16);
            rb0 = *(const float4*)(Bp);
            rb1 = *(const float4*)(Bp + 16);
        }
#pragma unroll
        for (int k = 0; k < TK; k++) {
            ulonglong2 aP = *(const ulonglong2*)&As[buf][k][ty * 4];
            float4 b = *(const float4*)&Bs[buf][k][tx * 4];
            u64 b0 = pack2(b.x), b1 = pack2(b.y), b2 = pack2(b.z), b3 = pack2(b.w);
            ffma2(accP[0][0], aP.x, b0); ffma2(accP[0][1], aP.x, b1);
            ffma2(accP[0][2], aP.x, b2); ffma2(accP[0][3], aP.x, b3);
            ffma2(accP[1][0], aP.y, b0); ffma2(accP[1][1], aP.y, b1);
            ffma2(accP[1][2], aP.y, b2); ffma2(accP[1][3], aP.y, b3);
        }
        if (kt + 1 < nk) {
            STORE_TILE(buf ^ 1);
            __syncthreads();
            buf ^= 1;
        }
    }
#undef STORE_TILE

#pragma unroll
    for (int p = 0; p < 2; p++) {
        float2 c0 = unpack2(accP[p][0]);
        float2 c1 = unpack2(accP[p][1]);
        float2 c2 = unpack2(accP[p][2]);
        float2 c3 = unpack2(accP[p][3]);
        *(float4*)(C + (size_t)(ty * 4 + 2 * p)     * ldc + tx * 4)
            = make_float4(c0.x, c1.x, c2.x, c3.x);
        *(float4*)(C + (size_t)(ty * 4 + 2 * p + 1) * ldc + tx * 4)
            = make_float4(c0.y, c1.y, c2.y, c3.y);
    }
}

// ---------------------------------------------------------------------------
// Setup kernels
// ---------------------------------------------------------------------------
__global__ void build_wcat(const float* __restrict__ W_ih,
                           const float* __restrict__ W_hh)
{
    size_t total = (size_t)NGATE * KCAT;
    for (size_t i = (size_t)blockIdx.x * blockDim.x + threadIdx.x; i < total;
         i += (size_t)gridDim.x * blockDim.x) {
        int j = (int)(i / KCAT);
        int k = (int)(i % KCAT);
        g_wcat[i] = (k < EMBD) ? W_ih[(size_t)j * EMBD + k]
                               : W_hh[(size_t)j * HH + (k - EMBD)];
    }
}

__global__ void init_state(const float* __restrict__ dec_init)
{
    int idx = blockIdx.x * blockDim.x + threadIdx.x;   // B*H
    int b = idx >> 10, j = idx & 1023;
    float h0 = dec_init[idx];
    g_hc[b * 2048 + j] = h0;
    g_xcat[b * KCAT + EMBD + j] = h0;
    g_c[idx] = dec_init[BB * HH + idx];
    if (j < EMBD) g_xcat[b * KCAT + j] = 0.f;
}

// ---------------------------------------------------------------------------
// LSTM cell (float4): sum GSPLIT gate partials + bias, apply nonlinearity
// ---------------------------------------------------------------------------
__device__ __forceinline__ float sigf(float x) { return 1.f / (1.f + expf(-x)); }

__global__ void __launch_bounds__(256)
lstm_cell(const float* __restrict__ b_lstm)
{
    int q = blockIdx.x * blockDim.x + threadIdx.x;     // 0..B*H/4-1
    int base = q * 4;
    int b = base >> 10, j = base & 1023;
    const float* gp = g_gpart + (size_t)b * NGATE;
    const size_t SP = (size_t)BB * NGATE;

    float4 ig = *(const float4*)&b_lstm[j];
    float4 fg = *(const float4*)&b_lstm[1024 + j];
    float4 gg = *(const float4*)&b_lstm[2048 + j];
    float4 og = *(const float4*)&b_lstm[3072 + j];
#pragma unroll
    for (int s = 0; s < GSPLIT; s++) {
        const float* p = gp + s * SP;
        float4 v;
        v = *(const float4*)&p[j];        ig.x+=v.x; ig.y+=v.y; ig.z+=v.z; ig.w+=v.w;
        v = *(const float4*)&p[1024 + j]; fg.x+=v.x; fg.y+=v.y; fg.z+=v.z; fg.w+=v.w;
        v = *(const float4*)&p[2048 + j]; gg.x+=v.x; gg.y+=v.y; gg.z+=v.z; gg.w+=v.w;
        v = *(const float4*)&p[3072 + j]; og.x+=v.x; og.y+=v.y; og.z+=v.z; og.w+=v.w;
    }
    float4 cold = *(const float4*)&g_c[base];
    float4 c, h;
    c.x = sigf(fg.x) * cold.x + sigf(ig.x) * tanhf(gg.x);
    c.y = sigf(fg.y) * cold.y + sigf(ig.y) * tanhf(gg.y);
    c.z = sigf(fg.z) * cold.z + sigf(ig.z) * tanhf(gg.z);
    c.w = sigf(fg.w) * cold.w + sigf(ig.w) * tanhf(gg.w);
    h.x = sigf(og.x) * tanhf(c.x);
    h.y = sigf(og.y) * tanhf(c.y);
    h.z = sigf(og.z) * tanhf(c.z);
    h.w = sigf(og.w) * tanhf(c.w);
    *(float4*)&g_c[base] = c;
    *(float4*)&g_hc[b * 2048 + j] = h;
    *(float4*)&g_xcat[b * KCAT + EMBD + j] = h;
}

// ---------------------------------------------------------------------------
// Attention scores: grid (16, B); one score row per warp; masked rows skipped
// ---------------------------------------------------------------------------
__global__ void __launch_bounds__(256)
attn_scores(const int* __restrict__ enc_len)
{
    int b = blockIdx.y;
    int tid = threadIdx.x, warp = tid >> 5, lane = tid & 31;
    __shared__ float4 sh4[HH / 4];

    const float4* h4 = (const float4*)&g_hc[b * 2048];
    sh4[tid] = h4[tid];
    __syncthreads();

    int s = blockIdx.x * 8 + warp;
    if (s >= enc_len[b]) return;              // masked row: skip 4KB read

    const float4* k4 = (const float4*)&g_keys[((size_t)b * SS + s) * HH];
    float acc = 0.f;
#pragma unroll
    for (int i = 0; i < 8; i++) {
        float4 kv = k4[lane + 32 * i];
        float4 hv = sh4[lane + 32 * i];
        acc = fmaf(kv.x, hv.x, acc);
        acc = fmaf(kv.y, hv.y, acc);
        acc = fmaf(kv.z, hv.z, acc);
        acc = fmaf(kv.w, hv.w, acc);
    }
#pragma unroll
    for (int o = 16; o; o >>= 1) acc += __shfl_xor_sync(0xffffffffu, acc, o);
    if (lane == 0) g_scores[b * SS + s] = acc;
}

// ---------------------------------------------------------------------------
// Attention context (softmax fused, recomputed per block): grid (4, B)
// ---------------------------------------------------------------------------
__global__ void __launch_bounds__(256)
attn_context(const float* __restrict__ enc, const int* __restrict__ enc_len)
{
    int b = blockIdx.y, e0 = blockIdx.x * 256;
    int tid = threadIdx.x, warp = tid >> 5, lane = tid & 31;
    __shared__ float sa[SS];
    __shared__ float red[8];
    __shared__ float bc;

    int len = enc_len[b];
    float v = -1e9f;
    if (tid < SS) {
        v = (tid < len) ? g_scores[b * SS + tid] : -1e9f;
        sa[tid] = v;
    }
    float m = v;
#pragma unroll
    for (int o = 16; o; o >>= 1) m = fmaxf(m, __shfl_xor_sync(0xffffffffu, m, o));
    if (lane == 0) red[warp] = m;
    __syncthreads();
    if (tid == 0) {
        float mm = red[0];
        for (int i = 1; i < 4; i++) mm = fmaxf(mm, red[i]);
        bc = mm;
    }
    __syncthreads();
    float mx = bc;

    float e = (tid < SS) ? expf(v - mx) : 0.f;
    float s2 = e;
#pragma unroll
    for (int o = 16; o; o >>= 1) s2 += __shfl_xor_sync(0xffffffffu, s2, o);
    __syncthreads();
    if (lane == 0) red[warp] = s2;
    __syncthreads();
    if (tid == 0) bc = red[0] + red[1] + red[2] + red[3];
    __syncthreads();
    float inv = 1.f / bc;
    if (tid < SS) sa[tid] = e * inv;
    __syncthreads();

    const float* ep = enc + ((size_t)b * SS) * EE + e0 + tid;
    float acc = 0.f;
    int s = 0;
    for (; s + 8 <= len; s += 8) {
        float x0 = ep[(size_t)(s + 0) * EE];
        float x1 = ep[(size_t)(s + 1) * EE];
        float x2 = ep[(size_t)(s + 2) * EE];
        float x3 = ep[(size_t)(s + 3) * EE];
        float x4 = ep[(size_t)(s + 4) * EE];
        float x5 = ep[(size_t)(s + 5) * EE];
        float x6 = ep[(size_t)(s + 6) * EE];
        float x7 = ep[(size_t)(s + 7) * EE];
        acc = fmaf(sa[s + 0], x0, acc);
        acc = fmaf(sa[s + 1], x1, acc);
        acc = fmaf(sa[s + 2], x2, acc);
        acc = fmaf(sa[s + 3], x3, acc);
        acc = fmaf(sa[s + 4], x4, acc);
        acc = fmaf(sa[s + 5], x5, acc);
        acc = fmaf(sa[s + 6], x6, acc);
        acc = fmaf(sa[s + 7], x7, acc);
    }
    for (; s < len; s++) acc = fmaf(sa[s], ep[(size_t)s * EE], acc);
    g_hc[b * 2048 + HH + e0 + tid] = acc;
}

// ---------------------------------------------------------------------------
// Reduce out-projection split-K partials (float4)
// ---------------------------------------------------------------------------
__global__ void __launch_bounds__(256)
reduce_dec()
{
    int q = blockIdx.x * blockDim.x + threadIdx.x;
    float4 a = make_float4(0.f, 0.f, 0.f, 0.f);
#pragma unroll
    for (int s = 0; s < OSPLIT; s++) {
        float4 v = *(const float4*)&g_dpart[(size_t)s * BB * EMBD + q * 4];
        a.x += v.x; a.y += v.y; a.z += v.z; a.w += v.w;
    }
    *(float4*)&g_dec[q * 4] = a;
}

// ---------------------------------------------------------------------------
// Final argmax from per-tile partials (250 entries per batch row) + embed
// ---------------------------------------------------------------------------
__global__ void __launch_bounds__(256)
argmax_final(const float* __restrict__ emb)
{
    int b = blockIdx.x;
    int tid = threadIdx.x, warp = tid >> 5, lane = tid & 31;

    float bv = -INFINITY;
    int   bi = 0x7fffffff;
    for (int i = tid; i < VTILES; i += 256) {
        float2 e = g_pmax[i * BB + b];
        float v = e.x; int ix = __float_as_int(e.y);
        if (v > bv || (v == bv && ix < bi)) { bv = v; bi = ix; }
    }
#pragma unroll
    for (int o = 16; o; o >>= 1) {
        float ov = __shfl_xor_sync(0xffffffffu, bv, o);
        int   oi = __shfl_xor_sync(0xffffffffu, bi, o);
        if (ov > bv || (ov == bv && oi < bi)) { bv = ov; bi = oi; }
    }
    __shared__ float sv[8];
    __shared__ int   si[8];
    __shared__ int   ssym;
    if (lane == 0) { sv[warp] = bv; si[warp] = bi; }
    __syncthreads();
    if (tid == 0) {
        bv = sv[0]; bi = si[0];
        for (int i = 1; i < 8; i++) {
            if (sv[i] > bv || (sv[i] == bv && si[i] < bi)) { bv = sv[i]; bi = si[i]; }
        }
        ssym = bi;
    }
    __syncthreads();
    int sym = ssym;
    if (tid < EMBD / 4) {
        const float4* er = (const float4*)(emb + (size_t)sym * EMBD);
        ((float4*)&g_xcat[b * KCAT])[tid] = er[tid];
    }
}

// ---------------------------------------------------------------------------
// Per-step in-place log-softmax over out[b, t, :] — runs on a side stream
// ---------------------------------------------------------------------------
__global__ void __launch_bounds__(1024)
logsoftmax_step(float* __restrict__ out, int t)
{
    float* p = out + ((size_t)blockIdx.x * TT + t) * VV;
    int tid = threadIdx.x;

    float x[32];
    float mx = -INFINITY;
#pragma unroll
    for (int i = 0; i < 32; i++) {
        int v = tid + (i << 10);
        x[i] = (v < VV) ? p[v] : -INFINITY;
        mx = fmaxf(mx, x[i]);
    }
    __shared__ float red[32];
    __shared__ float bc;
#pragma unroll
    for (int o = 16; o; o >>= 1) mx = fmaxf(mx, __shfl_xor_sync(0xffffffffu, mx, o));
    if ((tid & 31) == 0) red[tid >> 5] = mx;
    __syncthreads();
    if (tid < 32) {
        float m = red[tid];
#pragma unroll
        for (int o = 16; o; o >>= 1) m = fmaxf(m, __shfl_xor_sync(0xffffffffu, m, o));
        if (tid == 0) bc = m;
    }
    __syncthreads();
    float M = bc;

    float s = 0.f;
#pragma unroll
    for (int i = 0; i < 32; i++) s += expf(x[i] - M);
    __syncthreads();
#pragma unroll
    for (int o = 16; o; o >>= 1) s += __shfl_xor_sync(0xffffffffu, s, o);
    if ((tid & 31) == 0) red[tid >> 5] = s;
    __syncthreads();
    if (tid < 32) {
        float m = red[tid];
#pragma unroll
        for (int o = 16; o; o >>= 1) m += __shfl_xor_sync(0xffffffffu, m, o);
        if (tid == 0) bc = m;
    }
    __syncthreads();
    float lz = M + logf(bc);
#pragma unroll
    for (int i = 0; i < 32; i++) {
        int v = tid + (i << 10);
        if (v < VV) p[v] = x[i] - lz;
    }
}

__global__ void fill_tail(float* __restrict__ p, long n, float val)
{
    long i = (long)blockIdx.x * blockDim.x + threadIdx.x;
    if (i < n) p[i] = val;
}

// ---------------------------------------------------------------------------
// Launch
// ---------------------------------------------------------------------------
extern "C" void kernel_launch(void* const* d_in, const int* in_sizes, int n_in,
                              void* d_out, int out_size)
{
    const float* dec_init  = (const float*)d_in[0];
    const float* enc       = (const float*)d_in[1];
    const int*   enc_len   = (const int*)d_in[2];
    /* d_in[3] = tgt (unused in eval mode) */
    const float* W_ih      = (const float*)d_in[4];
    const float* W_hh      = (const float*)d_in[5];
    const float* b_lstm    = (const float*)d_in[6];
    const float* W_attproj = (const float*)d_in[7];
    const float* W_out     = (const float*)d_in[8];
    const float* W_vocab   = (const float*)d_in[9];
    const float* emb       = (const float*)d_in[10];
    float* out = (float*)d_out;

    void *p_keys, *p_wcat, *p_xcat, *p_hc, *p_gpart, *p_dpart, *p_dec;
    cudaGetSymbolAddress(&p_keys,  g_keys);
    cudaGetSymbolAddress(&p_wcat,  g_wcat);
    cudaGetSymbolAddress(&p_xcat,  g_xcat);
    cudaGetSymbolAddress(&p_hc,    g_hc);
    cudaGetSymbolAddress(&p_gpart, g_gpart);
    cudaGetSymbolAddress(&p_dpart, g_dpart);
    cudaGetSymbolAddress(&p_dec,   g_dec);

    // side stream + events for overlapping the per-step log-softmax
    // (created per call; never destroyed — kernel_launch runs only a handful
    //  of times, graph replays do not re-enter this function)
    cudaStream_t s2;
    cudaEvent_t  ev, evj;
    cudaStreamCreateWithFlags(&s2, cudaStreamNonBlocking);
    cudaEventCreateWithFlags(&ev,  cudaEventDisableTiming);
    cudaEventCreateWithFlags(&evj, cudaEventDisableTiming);

    // one-time setup
    build_wcat<<<2048, 256>>>(W_ih, W_hh);
    init_state<<<(BB * HH) / 256, 256>>>(dec_init);
    // keys[B*S, H] = enc[B*S, E] @ W_attproj^T   (masked: fully-dead m-tiles skip)
    sgemm128<<<dim3(HH / 128, (BB * SS) / 64, 1), 256>>>(
        enc, EE, W_attproj, EE, (float*)p_keys, HH, 0, EE, enc_len, nullptr);

    for (int t = 0; t < TT; t++) {
        // gates partials: split-K x8  (32 x 8 = 256 blocks, kLen=192)
        sgemm128<<<dim3(NGATE / 128, 1, GSPLIT), 256>>>(
            (const float*)p_xcat, KCAT, (const float*)p_wcat, KCAT,
            (float*)p_gpart, NGATE, (size_t)BB * NGATE, KCAT / GSPLIT,
            nullptr, nullptr);
        lstm_cell<<<(BB * HH / 4) / 256, 256>>>(b_lstm);
        attn_scores<<<dim3(16, BB), 256>>>(enc_len);
        attn_context<<<dim3(4, BB), 256>>>(enc, enc_len);
        // dec partials: split-K x32  (8 x 32 = 256 blocks, kLen=64)
        sgemm64<<<dim3(EMBD / 64, 1, OSPLIT), 256>>>(
            (const float*)p_hc, 2048, W_out, 2048,
            (float*)p_dpart, EMBD, (size_t)BB * EMBD, 2048 / OSPLIT);
        reduce_dec<<<(BB * EMBD / 4) / 256, 256>>>();
        // vocab logits into d_out[b,t,:] + fused per-tile argmax partials
        sgemm128<<<dim3(VV / 128, 1, 1), 256>>>(
            (const float*)p_dec, EMBD, W_vocab, EMBD,
            out + (size_t)t * VV, (size_t)TT * VV, 0, EMBD,
            nullptr, (float2*)1 /* enable pmax path */);
        // fork: log-softmax of step t runs on s2, off the critical path
        cudaEventRecord(ev, 0);
        cudaStreamWaitEvent(s2, ev, 0);
        logsoftmax_step<<<BB, 1024, 0, s2>>>(out, t);
        // critical path continues: argmax from partials + embedding gather
        argmax_final<<<BB, 256>>>(emb);
    }

    // join side stream back into the main stream before the tail
    cudaEventRecord(evj, s2);
    cudaStreamWaitEvent(0, evj, 0);

    // tgt_len output: always T (== 50) per the reference's final where()
    long extra = (long)out_size - (long)BB * TT * VV;
    if (extra < 0) extra = 0;
    fill_tail<<<(unsigned)((extra + 255) / 256) + 1, 256>>>(
        out + (size_t)BB * TT * VV, extra, 50.0f);
}